// round 5
// baseline (speedup 1.0000x reference)
#include <cuda_runtime.h>

// Problem constants
#define BB 8
#define CC 64
#define HH 256
#define WW 256
#define PLANE (HH*WW)
#define EPSN 1e-5f
#define SLOPE 0.01f
#define NOFF 169           // 13x13 shift search
#define CROP 244           // 256 - 2*6
#define NCROP (CROP*CROP)  // 59536

// ---------------------------------------------------------------------------
// Packed f32x2 helpers (sm_100+). Each lane is IEEE fp32 — bitwise identical
// to scalar FFMA; ptxas never auto-generates FFMA2 (SASS_QUICKREF), so we
// emit it by hand for 2x FMA issue throughput.
// ---------------------------------------------------------------------------
__device__ __forceinline__ unsigned long long fma2(unsigned long long a,
                                                   unsigned long long b,
                                                   unsigned long long c) {
    unsigned long long d;
    asm("fma.rn.f32x2 %0, %1, %2, %3;" : "=l"(d) : "l"(a), "l"(b), "l"(c));
    return d;
}
__device__ __forceinline__ unsigned long long bcast2(float v) {
    unsigned long long p;
    unsigned int u = __float_as_uint(v);
    asm("mov.b64 %0, {%1, %1};" : "=l"(p) : "r"(u));
    return p;
}
__device__ __forceinline__ void unpack2(unsigned long long p, float& lo, float& hi) {
    unsigned int a, b;
    asm("mov.b64 {%0, %1}, %2;" : "=r"(a), "=r"(b) : "l"(p));
    lo = __uint_as_float(a);   // first-stored float (even oc)
    hi = __uint_as_float(b);   // second-stored float (odd oc)
}

// ---------------------------------------------------------------------------
// Scratch (device globals; no allocation allowed)
// ---------------------------------------------------------------------------
__device__ float g_bufA[BB*CC*PLANE];
__device__ float g_bufB[BB*CC*PLANE];
__device__ float g_stats[8*BB*CC*2];   // per layer: (sum, sumsq) per (b,c)
__device__ float g_hr[BB*PLANE];
__device__ float g_loss[NOFF*BB];      // variance per (offset, batch)

// ---------------------------------------------------------------------------
// Zero the stats accumulators (must happen every launch; graph replays reuse)
// ---------------------------------------------------------------------------
__global__ void zero_stats_kernel() {
    int i = blockIdx.x * blockDim.x + threadIdx.x;
    if (i < 8*BB*CC*2) g_stats[i] = 0.f;
}

// ---------------------------------------------------------------------------
// Conv 3x3 (replication pad 1) -> raw output (+ per-(b,c) stats via atomics).
// Input is RAW previous-layer conv output; InstanceNorm + LeakyReLU are
// applied on load (NORM=true). Bias is skipped: it cancels exactly under
// InstanceNorm (mean absorbs it).
//
// Software-pipelined over ic with a double-buffered patch: while computing
// from patch[ic&1], the LDG/STS for ic+1 fill patch[(ic+1)&1]; one barrier
// per iteration covers "next ready" + "current free". LDG latency hides
// behind the 288-FFMA2 compute block.
//
// Block: 256 threads. Output tile 32x32 pixels, 16 output channels.
// Each thread: 2x2 pixels x 16 oc = 64 fp32 accumulators as 32 f32x2 pairs.
// grid = (8, 8, B*4): x,y = tile, z = b*4 + oc_group
// ---------------------------------------------------------------------------
template<int CIN, bool NORM>
__global__ void __launch_bounds__(256)
conv_kernel(const float* __restrict__ in,
            const float* __restrict__ wgt,       // [64][CIN][3][3]
            const float* __restrict__ stats_in,  // [B*CIN][2] (sum, sumsq)
            float* __restrict__ out,             // [B][64][H][W]
            float* __restrict__ stats_out)       // [B*64][2]
{
    __shared__ float w_s[CIN*9*16];     // [ic][tap][oc] for this oc-group
    __shared__ float patch[2][34*34];   // double-buffered input tile

    const int b   = blockIdx.z >> 2;
    const int ocg = blockIdx.z & 3;
    const int x0  = blockIdx.x * 32;
    const int y0  = blockIdx.y * 32;
    const int t   = threadIdx.x;

    // Stage weights for this oc-group: w_s[(ic*9+tap)*16 + oc]
    for (int i = t; i < CIN*9*16; i += 256) {
        int oc = i & 15, rest = i >> 4;      // rest = ic*9 + tap
        w_s[i] = wgt[(ocg*16 + oc)*(CIN*9) + rest];
    }

    // acc2[py][px][q]: packed pair (oc = 2q, 2q+1)
    unsigned long long acc2[2][2][8];
    #pragma unroll
    for (int py = 0; py < 2; py++)
        #pragma unroll
        for (int px = 0; px < 2; px++)
            #pragma unroll
            for (int q = 0; q < 8; q++) acc2[py][px][q] = 0ull;

    const int txx = t & 15, tyy = t >> 4;
    const int r0 = tyy*2, c0 = txx*2;

    // Patch loader: edge clamp (= replication pad 1) + optional norm+lrelu.
    auto load_patch = [&](int buf, int ic) {
        const float* ip = in + (size_t)(b*CIN + ic)*PLANE;
        float m = 0.f, rs = 0.f;
        if (NORM) {
            float s  = stats_in[(b*CIN + ic)*2 + 0];
            float s2 = stats_in[(b*CIN + ic)*2 + 1];
            m = s * (1.f/65536.f);
            float var = fmaxf(s2 * (1.f/65536.f) - m*m, 0.f);
            rs = rsqrtf(var + EPSN);
        }
        #pragma unroll
        for (int i = t; i < 34*34; i += 256) {
            int r = i / 34, c = i - r*34;
            int gy = y0 + r - 1; gy = max(0, min(gy, HH-1));
            int gx = x0 + c - 1; gx = max(0, min(gx, WW-1));
            float v = ip[gy*WW + gx];
            if (NORM) { v = (v - m) * rs; v = (v >= 0.f) ? v : SLOPE*v; }
            patch[buf][i] = v;
        }
    };

    // Prologue: fill buffer 0 for ic=0 (weights barrier folded in)
    load_patch(0, 0);
    __syncthreads();

    for (int ic = 0; ic < CIN; ic++) {
        const int cur = ic & 1;
        // Prefetch next channel into the other buffer (overlaps with FMAs)
        if (ic + 1 < CIN) load_patch(cur ^ 1, ic + 1);

        // Pixel values, broadcast-packed once per ic
        unsigned long long iv2[4][4];
        #pragma unroll
        for (int i = 0; i < 4; i++)
            #pragma unroll
            for (int j = 0; j < 4; j++)
                iv2[i][j] = bcast2(patch[cur][(r0 + i)*34 + (c0 + j)]);

        #pragma unroll
        for (int kr = 0; kr < 3; kr++)
            #pragma unroll
            for (int kc = 0; kc < 3; kc++) {
                const ulonglong2* wr =
                    (const ulonglong2*)&w_s[(ic*9 + kr*3 + kc)*16];
                #pragma unroll
                for (int h = 0; h < 4; h++) {
                    ulonglong2 wq = wr[h];   // warp-broadcast LDS.128: 2 oc-pairs
                    #pragma unroll
                    for (int py = 0; py < 2; py++)
                        #pragma unroll
                        for (int px = 0; px < 2; px++) {
                            unsigned long long x2 = iv2[py + kr][px + kc];
                            acc2[py][px][h*2+0] = fma2(x2, wq.x, acc2[py][px][h*2+0]);
                            acc2[py][px][h*2+1] = fma2(x2, wq.y, acc2[py][px][h*2+1]);
                        }
                }
            }
        // One barrier: next buffer complete + current buffer reusable
        __syncthreads();
    }

    // Unpack, write raw outputs (float2 coalesced) + per-channel stats
    float acc[2][2][16];
    #pragma unroll
    for (int py = 0; py < 2; py++)
        #pragma unroll
        for (int px = 0; px < 2; px++)
            #pragma unroll
            for (int q = 0; q < 8; q++)
                unpack2(acc2[py][px][q], acc[py][px][2*q], acc[py][px][2*q+1]);

    const int lane = t & 31;
    #pragma unroll
    for (int oc = 0; oc < 16; oc++) {
        int c = ocg*16 + oc;
        float* op = out + (size_t)(b*CC + c)*PLANE;
        #pragma unroll
        for (int py = 0; py < 2; py++) {
            int gy = y0 + r0 + py;
            float2 v = make_float2(acc[py][0][oc], acc[py][1][oc]);
            *(float2*)&op[gy*WW + x0 + c0] = v;
        }
        float s  = acc[0][0][oc] + acc[0][1][oc] + acc[1][0][oc] + acc[1][1][oc];
        float s2 = acc[0][0][oc]*acc[0][0][oc] + acc[0][1][oc]*acc[0][1][oc]
                 + acc[1][0][oc]*acc[1][0][oc] + acc[1][1][oc]*acc[1][1][oc];
        #pragma unroll
        for (int d = 16; d > 0; d >>= 1) {
            s  += __shfl_down_sync(0xffffffffu, s,  d);
            s2 += __shfl_down_sync(0xffffffffu, s2, d);
        }
        if (lane == 0) {
            atomicAdd(&stats_out[(b*CC + c)*2 + 0], s);
            atomicAdd(&stats_out[(b*CC + c)*2 + 1], s2);
        }
    }
}

// ---------------------------------------------------------------------------
// Projection: 64 -> 1 conv (norm+lrelu on load) + bias + residual xIn.
// grid = (16, 16, B), 256 threads, 1 pixel/thread (tile 16x16).
// ---------------------------------------------------------------------------
__global__ void __launch_bounds__(256)
proj_kernel(const float* __restrict__ in,
            const float* __restrict__ stats_in,
            const float* __restrict__ wp,     // [64][3][3]
            const float* __restrict__ bp,     // [1]
            const float* __restrict__ xIn,
            float* __restrict__ hr,
            float* __restrict__ dout,
            int write_dout)
{
    __shared__ float wsm[576];
    __shared__ float patch[2][18*18];
    const int b  = blockIdx.z;
    const int x0 = blockIdx.x * 16, y0 = blockIdx.y * 16;
    const int t  = threadIdx.x;
    const int tx = t & 15, ty = t >> 4;

    for (int i = t; i < 576; i += 256) wsm[i] = wp[i];

    auto load_patch = [&](int buf, int ic) {
        const float* ip = in + (size_t)(b*64 + ic)*PLANE;
        float s  = stats_in[(b*64 + ic)*2 + 0];
        float s2 = stats_in[(b*64 + ic)*2 + 1];
        float m  = s * (1.f/65536.f);
        float rs = rsqrtf(fmaxf(s2 * (1.f/65536.f) - m*m, 0.f) + EPSN);
        #pragma unroll
        for (int i = t; i < 18*18; i += 256) {
            int r = i / 18, c = i - r*18;
            int gy = max(0, min(y0 + r - 1, HH-1));
            int gx = max(0, min(x0 + c - 1, WW-1));
            float v = ip[gy*WW + gx];
            v = (v - m) * rs; v = (v >= 0.f) ? v : SLOPE*v;
            patch[buf][i] = v;
        }
    };

    load_patch(0, 0);
    __syncthreads();

    float acc = 0.f;
    for (int ic = 0; ic < 64; ic++) {
        const int cur = ic & 1;
        if (ic + 1 < 64) load_patch(cur ^ 1, ic + 1);
        #pragma unroll
        for (int kr = 0; kr < 3; kr++)
            #pragma unroll
            for (int kc = 0; kc < 3; kc++)
                acc = fmaf(patch[cur][(ty + kr)*18 + tx + kc],
                           wsm[ic*9 + kr*3 + kc], acc);
        __syncthreads();
    }
    int gy = y0 + ty, gx = x0 + tx;
    float v = acc + bp[0] + xIn[(size_t)b*PLANE + gy*WW + gx];
    hr[(size_t)b*PLANE + gy*WW + gx] = v;
    if (write_dout) dout[(size_t)b*PLANE + gy*WW + gx] = v;
}

// ---------------------------------------------------------------------------
// Shift-search loss. losses[off,b] = Var(crop - t) over 244x244:
// the detached equalizer eq = mean(t - crop) makes the loss exactly the
// variance of d = crop - t. One block per (offset, batch).
// ---------------------------------------------------------------------------
__global__ void __launch_bounds__(256)
loss_partial_kernel(const float* __restrict__ hr,
                    const float* __restrict__ target)
{
    const int off = blockIdx.x;
    const int b   = blockIdx.y;
    const int dy  = off / 13, dx = off - dy*13;
    const float* hp = hr     + (size_t)b*PLANE;
    const float* tp = target + (size_t)b*PLANE;

    float s = 0.f, s2 = 0.f;
    for (int i = threadIdx.x; i < NCROP; i += 256) {
        int r = i / CROP, c = i - r*CROP;
        float d = hp[(dy + r)*WW + (dx + c)] - tp[(6 + r)*WW + (6 + c)];
        s += d;
        s2 = fmaf(d, d, s2);
    }
    __shared__ float sh[2][8];
    int lane = threadIdx.x & 31, w = threadIdx.x >> 5;
    #pragma unroll
    for (int d = 16; d > 0; d >>= 1) {
        s  += __shfl_down_sync(0xffffffffu, s,  d);
        s2 += __shfl_down_sync(0xffffffffu, s2, d);
    }
    if (lane == 0) { sh[0][w] = s; sh[1][w] = s2; }
    __syncthreads();
    if (threadIdx.x == 0) {
        float S = 0.f, S2 = 0.f;
        #pragma unroll
        for (int i = 0; i < 8; i++) { S += sh[0][i]; S2 += sh[1][i]; }
        const float invN = 1.f / (float)NCROP;
        float m = S * invN;
        g_loss[off*BB + b] = S2 * invN - m*m;
    }
}

__global__ void loss_final_kernel(float* __restrict__ dout, int out_size) {
    __shared__ float mins[8];
    int w = threadIdx.x >> 5, lane = threadIdx.x & 31;
    if (w < 8) {
        float mn = 3.4e38f;
        for (int off = lane; off < NOFF; off += 32)
            mn = fminf(mn, g_loss[off*BB + w]);
        #pragma unroll
        for (int d = 16; d > 0; d >>= 1)
            mn = fminf(mn, __shfl_down_sync(0xffffffffu, mn, d));
        if (lane == 0) mins[w] = mn;
    }
    __syncthreads();
    if (threadIdx.x == 0) {
        float s = 0.f;
        #pragma unroll
        for (int i = 0; i < 8; i++) s += mins[i];
        dout[out_size - 1] = s * (1.f/8.f);
    }
}

// ---------------------------------------------------------------------------
// Launcher. Inputs (metadata order): xIn, target, w0, b0, ws, bs, wp, bp.
// Output: hr (B*H*W floats) followed by scalar loss.
// ---------------------------------------------------------------------------
extern "C" void kernel_launch(void* const* d_in, const int* in_sizes, int n_in,
                              void* d_out, int out_size)
{
    const float* xIn    = (const float*)d_in[0];
    const float* target = (const float*)d_in[1];
    const float* w0     = (const float*)d_in[2];
    const float* ws     = (const float*)d_in[4];
    const float* wp     = (const float*)d_in[6];
    const float* bp     = (const float*)d_in[7];
    float* outp = (float*)d_out;

    float *bufA, *bufB, *stats, *hr;
    cudaGetSymbolAddress((void**)&bufA,  g_bufA);
    cudaGetSymbolAddress((void**)&bufB,  g_bufB);
    cudaGetSymbolAddress((void**)&stats, g_stats);
    cudaGetSymbolAddress((void**)&hr,    g_hr);

    zero_stats_kernel<<<32, 256>>>();

    dim3 cgrid(8, 8, BB*4);
    // Layer 0: 1 -> 64, no input norm
    conv_kernel<1, false><<<cgrid, 256>>>(xIn, w0, nullptr, bufA, stats);

    // Layers 1..7: 64 -> 64, norm+lrelu applied on input load
    float* cur = bufA;
    float* nxt = bufB;
    for (int l = 1; l <= 7; l++) {
        conv_kernel<64, true><<<cgrid, 256>>>(
            cur, ws + (size_t)(l-1)*64*64*9,
            stats + (l-1)*BB*CC*2, nxt, stats + l*BB*CC*2);
        float* tmp = cur; cur = nxt; nxt = tmp;
    }

    int write_dout = (out_size >= BB*PLANE + 1) ? 1 : 0;
    proj_kernel<<<dim3(16, 16, BB), 256>>>(
        cur, stats + 7*BB*CC*2, wp, bp, xIn, hr, outp, write_dout);

    loss_partial_kernel<<<dim3(NOFF, BB), 256>>>(hr, target);
    loss_final_kernel<<<1, 256>>>(outp, out_size);
}

// round 7
// speedup vs baseline: 1.0273x; 1.0273x over previous
#include <cuda_runtime.h>

// Problem constants
#define BB 8
#define CC 64
#define HH 256
#define WW 256
#define PLANE (HH*WW)
#define EPSN 1e-5f
#define SLOPE 0.01f
#define NOFF 169           // 13x13 shift search
#define CROP 244           // 256 - 2*6
#define NCROP (CROP*CROP)  // 59536

// ---------------------------------------------------------------------------
// Packed f32x2 helpers (sm_100+). Each lane is IEEE fp32; ptxas never
// auto-generates FFMA2 (SASS_QUICKREF), so emit by hand: 2x FMA per issue.
// ---------------------------------------------------------------------------
__device__ __forceinline__ unsigned long long fma2(unsigned long long a,
                                                   unsigned long long b,
                                                   unsigned long long c) {
    unsigned long long d;
    asm("fma.rn.f32x2 %0, %1, %2, %3;" : "=l"(d) : "l"(a), "l"(b), "l"(c));
    return d;
}
__device__ __forceinline__ unsigned long long bcast2(float v) {
    unsigned long long p;
    unsigned int u = __float_as_uint(v);
    asm("mov.b64 %0, {%1, %1};" : "=l"(p) : "r"(u));
    return p;
}
__device__ __forceinline__ void unpack2(unsigned long long p, float& lo, float& hi) {
    unsigned int a, b;
    asm("mov.b64 {%0, %1}, %2;" : "=r"(a), "=r"(b) : "l"(p));
    lo = __uint_as_float(a);
    hi = __uint_as_float(b);
}

// ---------------------------------------------------------------------------
// Scratch (device globals; no allocation allowed)
// ---------------------------------------------------------------------------
__device__ float g_bufA[BB*CC*PLANE];
__device__ float g_bufB[BB*CC*PLANE];
__device__ float g_stats[8*BB*CC*2];   // per layer: (sum, sumsq) per (b,c)
__device__ float g_hr[BB*PLANE];
__device__ float g_loss[NOFF*BB];      // variance per (offset, batch)

__global__ void zero_stats_kernel() {
    int i = blockIdx.x * blockDim.x + threadIdx.x;
    if (i < 8*BB*CC*2) g_stats[i] = 0.f;
}

// ---------------------------------------------------------------------------
// Conv 3x3 (replication pad 1) -> raw output (+ per-(b,c) stats via atomics).
// InstanceNorm + LeakyReLU applied on input load (NORM=true); trunk biases
// cancel under InstanceNorm.
//
// Pipeline per ic: [LDG next channel into regs] -> [288 FFMA2 from patch]
// -> [transform + STS next channel] -> barrier. LDG L2 latency (~234cyc) is
// covered by the FMA block; per-thread patch offsets (clamped replication
// pad addresses) are precomputed once — no div/clamp in the loop.
//
// Block: 256 threads. Tile 32x32 px, 16 oc. 64 accumulators as 32 f32x2.
// grid = (8, 8, B*4): z = b*4 + oc_group
// ---------------------------------------------------------------------------
template<int CIN, bool NORM>
__global__ void __launch_bounds__(256)
conv_kernel(const float* __restrict__ in,
            const float* __restrict__ wgt,       // [64][CIN][3][3]
            const float* __restrict__ stats_in,  // [B*CIN][2] (sum, sumsq)
            float* __restrict__ out,             // [B][64][H][W]
            float* __restrict__ stats_out)       // [B*64][2]
{
    __shared__ float w_s[CIN*9*16];     // [ic][tap][oc] for this oc-group
    __shared__ float patch[2][34*34];   // double-buffered input tile

    const int b   = blockIdx.z >> 2;
    const int ocg = blockIdx.z & 3;
    const int x0  = blockIdx.x * 32;
    const int y0  = blockIdx.y * 32;
    const int t   = threadIdx.x;

    // Stage weights for this oc-group: w_s[(ic*9+tap)*16 + oc]
    for (int i = t; i < CIN*9*16; i += 256) {
        int oc = i & 15, rest = i >> 4;
        w_s[i] = wgt[(ocg*16 + oc)*(CIN*9) + rest];
    }

    // Precompute per-thread patch-slot global offsets (loop-invariant):
    // slots 0..3 always valid; slot 4 only for t < 1156-1024 = 132.
    const bool has5 = (t < 34*34 - 4*256);
    int goff[5];
    #pragma unroll
    for (int k = 0; k < 5; k++) {
        int i = t + k*256;
        if (i < 34*34) {
            int r = i / 34, c = i - r*34;
            int gy = y0 + r - 1; gy = max(0, min(gy, HH-1));
            int gx = x0 + c - 1; gx = max(0, min(gx, WW-1));
            goff[k] = gy*WW + gx;
        }
    }

    const float* base = in + (size_t)b*CIN*PLANE;

    // LDG-early: raw loads + channel stats into registers
    float ld[5]; float nm, rs;   // v_norm = v*rs + nm
    auto ldg_ch = [&](int ic) {
        const float* ip = base + (size_t)ic*PLANE;
        #pragma unroll
        for (int k = 0; k < 4; k++) ld[k] = ip[goff[k]];
        if (has5) ld[4] = ip[goff[4]];
        if (NORM) {
            float2 st = *(const float2*)&stats_in[(b*CIN + ic)*2];
            float m   = st.x * (1.f/65536.f);
            float var = fmaxf(st.y * (1.f/65536.f) - m*m, 0.f);
            rs = rsqrtf(var + EPSN);
            nm = -m * rs;
        }
    };
    // STS-late: transform + store to smem
    auto sts_ch = [&](int buf) {
        #pragma unroll
        for (int k = 0; k < 5; k++) {
            if (k == 4 && !has5) break;
            float v = ld[k];
            if (NORM) { v = fmaf(v, rs, nm); v = (v >= 0.f) ? v : SLOPE*v; }
            patch[buf][t + k*256] = v;
        }
    };

    // acc2[py][px][q]: packed pair (oc = 2q, 2q+1)
    unsigned long long acc2[2][2][8];
    #pragma unroll
    for (int py = 0; py < 2; py++)
        #pragma unroll
        for (int px = 0; px < 2; px++)
            #pragma unroll
            for (int q = 0; q < 8; q++) acc2[py][px][q] = 0ull;

    const int txx = t & 15, tyy = t >> 4;
    const int r0 = tyy*2, c0 = txx*2;

    // Prologue: channel 0 into buffer 0 (also covers weight staging barrier)
    ldg_ch(0);
    sts_ch(0);
    __syncthreads();

    for (int ic = 0; ic < CIN; ic++) {
        const int cur = ic & 1;
        if (ic + 1 < CIN) ldg_ch(ic + 1);   // LDGs fly during the FMA block

        unsigned long long iv2[4][4];
        #pragma unroll
        for (int i = 0; i < 4; i++)
            #pragma unroll
            for (int j = 0; j < 4; j++)
                iv2[i][j] = bcast2(patch[cur][(r0 + i)*34 + (c0 + j)]);

        #pragma unroll
        for (int kr = 0; kr < 3; kr++)
            #pragma unroll
            for (int kc = 0; kc < 3; kc++) {
                const ulonglong2* wr =
                    (const ulonglong2*)&w_s[(ic*9 + kr*3 + kc)*16];
                #pragma unroll
                for (int h = 0; h < 4; h++) {
                    ulonglong2 wq = wr[h];   // warp-broadcast LDS.128
                    #pragma unroll
                    for (int py = 0; py < 2; py++)
                        #pragma unroll
                        for (int px = 0; px < 2; px++) {
                            unsigned long long x2 = iv2[py + kr][px + kc];
                            acc2[py][px][h*2+0] = fma2(x2, wq.x, acc2[py][px][h*2+0]);
                            acc2[py][px][h*2+1] = fma2(x2, wq.y, acc2[py][px][h*2+1]);
                        }
                }
            }

        if (ic + 1 < CIN) sts_ch(cur ^ 1);  // LDG results long since landed
        __syncthreads();
    }

    // Unpack, write raw outputs (float2 coalesced) + per-channel stats
    float acc[2][2][16];
    #pragma unroll
    for (int py = 0; py < 2; py++)
        #pragma unroll
        for (int px = 0; px < 2; px++)
            #pragma unroll
            for (int q = 0; q < 8; q++)
                unpack2(acc2[py][px][q], acc[py][px][2*q], acc[py][px][2*q+1]);

    const int lane = t & 31;
    #pragma unroll
    for (int oc = 0; oc < 16; oc++) {
        int c = ocg*16 + oc;
        float* op = out + (size_t)(b*CC + c)*PLANE;
        #pragma unroll
        for (int py = 0; py < 2; py++) {
            int gy = y0 + r0 + py;
            float2 v = make_float2(acc[py][0][oc], acc[py][1][oc]);
            *(float2*)&op[gy*WW + x0 + c0] = v;
        }
        float s  = acc[0][0][oc] + acc[0][1][oc] + acc[1][0][oc] + acc[1][1][oc];
        float s2 = acc[0][0][oc]*acc[0][0][oc] + acc[0][1][oc]*acc[0][1][oc]
                 + acc[1][0][oc]*acc[1][0][oc] + acc[1][1][oc]*acc[1][1][oc];
        #pragma unroll
        for (int d = 16; d > 0; d >>= 1) {
            s  += __shfl_down_sync(0xffffffffu, s,  d);
            s2 += __shfl_down_sync(0xffffffffu, s2, d);
        }
        if (lane == 0) {
            atomicAdd(&stats_out[(b*CC + c)*2 + 0], s);
            atomicAdd(&stats_out[(b*CC + c)*2 + 1], s2);
        }
    }
}

// ---------------------------------------------------------------------------
// Projection: 64 -> 1 conv (norm+lrelu on load) + bias + residual xIn.
// grid = (16, 16, B), 256 threads, 1 pixel/thread (tile 16x16).
// Same LDG-early/STS-late pipeline; 18x18=324 patch -> 2 slots/thread.
// ---------------------------------------------------------------------------
__global__ void __launch_bounds__(256)
proj_kernel(const float* __restrict__ in,
            const float* __restrict__ stats_in,
            const float* __restrict__ wp,     // [64][3][3]
            const float* __restrict__ bp,     // [1]
            const float* __restrict__ xIn,
            float* __restrict__ hr,
            float* __restrict__ dout,
            int write_dout)
{
    __shared__ float wsm[576];
    __shared__ float patch[2][18*18];
    const int b  = blockIdx.z;
    const int x0 = blockIdx.x * 16, y0 = blockIdx.y * 16;
    const int t  = threadIdx.x;
    const int tx = t & 15, ty = t >> 4;

    for (int i = t; i < 576; i += 256) wsm[i] = wp[i];

    const bool has2 = (t < 18*18 - 256);
    int goff[2];
    #pragma unroll
    for (int k = 0; k < 2; k++) {
        int i = t + k*256;
        if (i < 18*18) {
            int r = i / 18, c = i - r*18;
            int gy = max(0, min(y0 + r - 1, HH-1));
            int gx = max(0, min(x0 + c - 1, WW-1));
            goff[k] = gy*WW + gx;
        }
    }

    const float* base = in + (size_t)b*64*PLANE;
    float ld[2]; float nm, rs;
    auto ldg_ch = [&](int ic) {
        const float* ip = base + (size_t)ic*PLANE;
        if (t < 18*18) ld[0] = ip[goff[0]];
        if (has2)      ld[1] = ip[goff[1]];
        float2 st = *(const float2*)&stats_in[(b*64 + ic)*2];
        float m   = st.x * (1.f/65536.f);
        float var = fmaxf(st.y * (1.f/65536.f) - m*m, 0.f);
        rs = rsqrtf(var + EPSN);
        nm = -m * rs;
    };
    auto sts_ch = [&](int buf) {
        #pragma unroll
        for (int k = 0; k < 2; k++) {
            int i = t + k*256;
            if (i < 18*18) {
                float v = fmaf(ld[k], rs, nm);
                v = (v >= 0.f) ? v : SLOPE*v;
                patch[buf][i] = v;
            }
        }
    };

    ldg_ch(0);
    sts_ch(0);
    __syncthreads();

    float acc = 0.f;
    for (int ic = 0; ic < 64; ic++) {
        const int cur = ic & 1;
        if (ic + 1 < 64) ldg_ch(ic + 1);
        #pragma unroll
        for (int kr = 0; kr < 3; kr++)
            #pragma unroll
            for (int kc = 0; kc < 3; kc++)
                acc = fmaf(patch[cur][(ty + kr)*18 + tx + kc],
                           wsm[ic*9 + kr*3 + kc], acc);
        if (ic + 1 < 64) sts_ch(cur ^ 1);
        __syncthreads();
    }
    int gy = y0 + ty, gx = x0 + tx;
    float v = acc + bp[0] + xIn[(size_t)b*PLANE + gy*WW + gx];
    hr[(size_t)b*PLANE + gy*WW + gx] = v;
    if (write_dout) dout[(size_t)b*PLANE + gy*WW + gx] = v;
}

// ---------------------------------------------------------------------------
// Shift-search loss. losses[off,b] = Var(crop - t) over 244x244 (the
// detached equalizer makes the loss exactly the variance of crop - t).
// ---------------------------------------------------------------------------
__global__ void __launch_bounds__(256)
loss_partial_kernel(const float* __restrict__ hr,
                    const float* __restrict__ target)
{
    const int off = blockIdx.x;
    const int b   = blockIdx.y;
    const int dy  = off / 13, dx = off - dy*13;
    const float* hp = hr     + (size_t)b*PLANE;
    const float* tp = target + (size_t)b*PLANE;

    float s = 0.f, s2 = 0.f;
    for (int i = threadIdx.x; i < NCROP; i += 256) {
        int r = i / CROP, c = i - r*CROP;
        float d = hp[(dy + r)*WW + (dx + c)] - tp[(6 + r)*WW + (6 + c)];
        s += d;
        s2 = fmaf(d, d, s2);
    }
    __shared__ float sh[2][8];
    int lane = threadIdx.x & 31, w = threadIdx.x >> 5;
    #pragma unroll
    for (int d = 16; d > 0; d >>= 1) {
        s  += __shfl_down_sync(0xffffffffu, s,  d);
        s2 += __shfl_down_sync(0xffffffffu, s2, d);
    }
    if (lane == 0) { sh[0][w] = s; sh[1][w] = s2; }
    __syncthreads();
    if (threadIdx.x == 0) {
        float S = 0.f, S2 = 0.f;
        #pragma unroll
        for (int i = 0; i < 8; i++) { S += sh[0][i]; S2 += sh[1][i]; }
        const float invN = 1.f / (float)NCROP;
        float m = S * invN;
        g_loss[off*BB + b] = S2 * invN - m*m;
    }
}

__global__ void loss_final_kernel(float* __restrict__ dout, int out_size) {
    __shared__ float mins[8];
    int w = threadIdx.x >> 5, lane = threadIdx.x & 31;
    if (w < 8) {
        float mn = 3.4e38f;
        for (int off = lane; off < NOFF; off += 32)
            mn = fminf(mn, g_loss[off*BB + w]);
        #pragma unroll
        for (int d = 16; d > 0; d >>= 1)
            mn = fminf(mn, __shfl_down_sync(0xffffffffu, mn, d));
        if (lane == 0) mins[w] = mn;
    }
    __syncthreads();
    if (threadIdx.x == 0) {
        float s = 0.f;
        #pragma unroll
        for (int i = 0; i < 8; i++) s += mins[i];
        dout[out_size - 1] = s * (1.f/8.f);
    }
}

// ---------------------------------------------------------------------------
// Launcher. Inputs (metadata order): xIn, target, w0, b0, ws, bs, wp, bp.
// Output: hr (B*H*W floats) followed by scalar loss.
// ---------------------------------------------------------------------------
extern "C" void kernel_launch(void* const* d_in, const int* in_sizes, int n_in,
                              void* d_out, int out_size)
{
    const float* xIn    = (const float*)d_in[0];
    const float* target = (const float*)d_in[1];
    const float* w0     = (const float*)d_in[2];
    const float* ws     = (const float*)d_in[4];
    const float* wp     = (const float*)d_in[6];
    const float* bp     = (const float*)d_in[7];
    float* outp = (float*)d_out;

    float *bufA, *bufB, *stats, *hr;
    cudaGetSymbolAddress((void**)&bufA,  g_bufA);
    cudaGetSymbolAddress((void**)&bufB,  g_bufB);
    cudaGetSymbolAddress((void**)&stats, g_stats);
    cudaGetSymbolAddress((void**)&hr,    g_hr);

    zero_stats_kernel<<<32, 256>>>();

    dim3 cgrid(8, 8, BB*4);
    // Layer 0: 1 -> 64, no input norm
    conv_kernel<1, false><<<cgrid, 256>>>(xIn, w0, nullptr, bufA, stats);

    // Layers 1..7: 64 -> 64, norm+lrelu applied on input load
    float* cur = bufA;
    float* nxt = bufB;
    for (int l = 1; l <= 7; l++) {
        conv_kernel<64, true><<<cgrid, 256>>>(
            cur, ws + (size_t)(l-1)*64*64*9,
            stats + (l-1)*BB*CC*2, nxt, stats + l*BB*CC*2);
        float* tmp = cur; cur = nxt; nxt = tmp;
    }

    int write_dout = (out_size >= BB*PLANE + 1) ? 1 : 0;
    proj_kernel<<<dim3(16, 16, BB), 256>>>(
        cur, stats + 7*BB*CC*2, wp, bp, xIn, hr, outp, write_dout);

    loss_partial_kernel<<<dim3(NOFF, BB), 256>>>(hr, target);
    loss_final_kernel<<<1, 256>>>(outp, out_size);
}